// round 2
// baseline (speedup 1.0000x reference)
#include <cuda_runtime.h>

#define EMB 64
#define NL_MAX 50000
#define NR_MAX 100000
#define NE_MAX 1000000
#define BN_EPS 1e-5f

// ---------------- scratch (static device globals; no runtime alloc) ----------
__device__ float d_LP[NL_MAX * EMB];     // left projection
__device__ float d_RP[NR_MAX * EMB];     // right projection
__device__ float d_S[NR_MAX * EMB];      // segment_sum(relu(bn1(joint)))
__device__ float d_conv[NR_MAX * EMB];   // S @ W_final.T + deg*b_final
__device__ float d_h[NR_MAX * EMB];      // hidden layer
__device__ float d_deg[NR_MAX];          // per-right-node degree (float)
__device__ float d_stats[256];           // [0:64) sum1, [64:128) sq1, [128:192) sum2, [192:256) sq2
__device__ float d_sc[256];              // [0:64) scale1, [64:128) shift1, [128:192) scale2, [192:256) shift2

// ---------------- zero scratch that is atomically accumulated ---------------
__global__ void zero_kernel(int nS, int nR) {
    int i = blockIdx.x * blockDim.x + threadIdx.x;
    if (i < nS) d_S[i] = 0.f;
    if (i < nR) d_deg[i] = 0.f;
    if (i < 256) d_stats[i] = 0.f;
}

// ---------------- generic 64-wide GEMM: out = f(X @ W.T (+bias terms)) ------
// MODE 0: out = X@W.T
// MODE 1: out = X@W.T + bias
// MODE 2: out = X@W.T + deg*bias ; accumulate column sum/sumsq -> d_stats[128..]
// MODE 3: out = relu(X@W.T + bias)
// Block: 256 threads. cols: thread owns (2*cg, 2*cg+1), cg = t&31.
// rows: 32 per block, thread handles 4 (rg = t>>5).
template <int MODE>
__global__ __launch_bounds__(256) void gemm64_kernel(
    const float* __restrict__ X, const float* __restrict__ W,
    const float* __restrict__ bias, const float* __restrict__ deg,
    float* __restrict__ out, int nrows)
{
    __shared__ float xs[32][EMB];
    int t = threadIdx.x;
    int cg = t & 31;
    int rg = t >> 5;
    int row0 = blockIdx.x * 32;
    int ca = 2 * cg, cb = 2 * cg + 1;

    // cooperative x tile load (coalesced)
#pragma unroll
    for (int i = 0; i < 8; i++) {
        int idx = t + i * 256;
        int r = idx >> 6, c = idx & 63;
        int gr = row0 + r;
        xs[r][c] = (gr < nrows) ? X[gr * EMB + c] : 0.f;
    }

    // W rows for this thread's two output columns -> registers
    float wa[EMB], wb[EMB];
#pragma unroll
    for (int k = 0; k < EMB; k++) {
        wa[k] = W[ca * EMB + k];
        wb[k] = W[cb * EMB + k];
    }
    __syncthreads();

    float accA[4], accB[4];
#pragma unroll
    for (int j = 0; j < 4; j++) {
        if (MODE == 1 || MODE == 3) {
            accA[j] = bias[ca];
            accB[j] = bias[cb];
        } else if (MODE == 2) {
            int gr = row0 + rg * 4 + j;
            float dv = (gr < nrows) ? deg[gr] : 0.f;
            accA[j] = dv * bias[ca];
            accB[j] = dv * bias[cb];
        } else {
            accA[j] = 0.f;
            accB[j] = 0.f;
        }
    }

#pragma unroll
    for (int k2 = 0; k2 < 32; k2++) {
#pragma unroll
        for (int j = 0; j < 4; j++) {
            float2 x2 = *(const float2*)&xs[rg * 4 + j][2 * k2];
            accA[j] = fmaf(x2.x, wa[2 * k2], accA[j]);
            accA[j] = fmaf(x2.y, wa[2 * k2 + 1], accA[j]);
            accB[j] = fmaf(x2.x, wb[2 * k2], accB[j]);
            accB[j] = fmaf(x2.y, wb[2 * k2 + 1], accB[j]);
        }
    }

    float sA = 0.f, qA = 0.f, sB = 0.f, qB = 0.f;
#pragma unroll
    for (int j = 0; j < 4; j++) {
        int gr = row0 + rg * 4 + j;
        if (gr < nrows) {
            float a = accA[j], b = accB[j];
            if (MODE == 3) { a = fmaxf(a, 0.f); b = fmaxf(b, 0.f); }
            ((float2*)out)[gr * 32 + cg] = make_float2(a, b);
            if (MODE == 2) { sA += a; qA += a * a; sB += b; qB += b * b; }
        }
    }

    if (MODE == 2) {
        __shared__ float red[128];
        if (t < 128) red[t] = 0.f;
        __syncthreads();
        atomicAdd(&red[ca], sA);
        atomicAdd(&red[64 + ca], qA);
        atomicAdd(&red[cb], sB);
        atomicAdd(&red[64 + cb], qB);
        __syncthreads();
        if (t < 128) atomicAdd(&d_stats[128 + t], red[t]);
    }
}

// ---------------- edge pass 1: bn1 column sums/sumsq + degree ---------------
// 16 threads per edge, each thread covers 4 contiguous cols (float4).
__global__ __launch_bounds__(256) void edge_stats_kernel(
    const int* __restrict__ ei, const float* __restrict__ ef,
    const float* __restrict__ Wedge, int NE)
{
    int t = threadIdx.x;
    int g = t & 15;
    float4 we = ((const float4*)Wedge)[g];
    float4 sum = make_float4(0.f, 0.f, 0.f, 0.f);
    float4 sq = make_float4(0.f, 0.f, 0.f, 0.f);

    for (int e = blockIdx.x * 16 + (t >> 4); e < NE; e += gridDim.x * 16) {
        int i0 = ei[e];
        int i1 = ei[NE + e];
        float f = ef[e];
        float4 lp = ((const float4*)d_LP)[i0 * 16 + g];
        float4 rp = ((const float4*)d_RP)[i1 * 16 + g];
        float4 j;
        j.x = fmaf(f, we.x, lp.x + rp.x);
        j.y = fmaf(f, we.y, lp.y + rp.y);
        j.z = fmaf(f, we.z, lp.z + rp.z);
        j.w = fmaf(f, we.w, lp.w + rp.w);
        sum.x += j.x; sum.y += j.y; sum.z += j.z; sum.w += j.w;
        sq.x += j.x * j.x; sq.y += j.y * j.y; sq.z += j.z * j.z; sq.w += j.w * j.w;
        if (g == 0) atomicAdd(&d_deg[i1], 1.f);
    }

    __shared__ float red[128];
    if (t < 128) red[t] = 0.f;
    __syncthreads();
    atomicAdd(&red[4 * g + 0], sum.x);
    atomicAdd(&red[4 * g + 1], sum.y);
    atomicAdd(&red[4 * g + 2], sum.z);
    atomicAdd(&red[4 * g + 3], sum.w);
    atomicAdd(&red[64 + 4 * g + 0], sq.x);
    atomicAdd(&red[64 + 4 * g + 1], sq.y);
    atomicAdd(&red[64 + 4 * g + 2], sq.z);
    atomicAdd(&red[64 + 4 * g + 3], sq.w);
    __syncthreads();
    if (t < 128) atomicAdd(&d_stats[t], red[t]);
}

// ---------------- batchnorm finalize: stats -> scale/shift ------------------
__global__ void bn_finalize_kernel(const float* __restrict__ gamma,
                                   const float* __restrict__ beta,
                                   float cnt, int soff, int ooff)
{
    int c = threadIdx.x;
    if (c < 64) {
        float mean = d_stats[soff + c] / cnt;
        float var = d_stats[soff + 64 + c] / cnt - mean * mean;
        float sc = gamma[c] * rsqrtf(var + BN_EPS);
        d_sc[ooff + c] = sc;
        d_sc[ooff + 64 + c] = beta[c] - mean * sc;
    }
}

// ---------------- edge pass 2: recompute joint, bn1+relu, scatter into S ----
__global__ __launch_bounds__(256) void edge_scatter_kernel(
    const int* __restrict__ ei, const float* __restrict__ ef,
    const float* __restrict__ Wedge, int NE)
{
    int tid = blockIdx.x * 256 + threadIdx.x;
    int e = tid >> 4;
    int g = tid & 15;
    if (e >= NE) return;

    float4 we = ((const float4*)Wedge)[g];
    float4 s = ((const float4*)d_sc)[g];        // scale1
    float4 sh = ((const float4*)d_sc)[16 + g];  // shift1

    int i0 = ei[e];
    int i1 = ei[NE + e];
    float f = ef[e];
    float4 lp = ((const float4*)d_LP)[i0 * 16 + g];
    float4 rp = ((const float4*)d_RP)[i1 * 16 + g];

    float4 v;
    v.x = fmaxf(fmaf(fmaf(f, we.x, lp.x + rp.x), s.x, sh.x), 0.f);
    v.y = fmaxf(fmaf(fmaf(f, we.y, lp.y + rp.y), s.y, sh.y), 0.f);
    v.z = fmaxf(fmaf(fmaf(f, we.z, lp.z + rp.z), s.z, sh.z), 0.f);
    v.w = fmaxf(fmaf(fmaf(f, we.w, lp.w + rp.w), s.w, sh.w), 0.f);

    float* p = &d_S[i1 * EMB + 4 * g];
    asm volatile("red.global.add.v4.f32 [%0], {%1,%2,%3,%4};"
                 :: "l"(p), "f"(v.x), "f"(v.y), "f"(v.z), "f"(v.w) : "memory");
}

// ---------------- output layer 1: h = relu([bn2(conv), right] @ W1.T + b1) --
__global__ __launch_bounds__(256) void out1_kernel(
    const float* __restrict__ conv, const float* __restrict__ right,
    const float* __restrict__ W1, const float* __restrict__ b1,
    float* __restrict__ out, int nrows)
{
    __shared__ float xs[32][EMB];
    int t = threadIdx.x;
    int cg = t & 31;
    int rg = t >> 5;
    int row0 = blockIdx.x * 32;
    int ca = 2 * cg, cb = 2 * cg + 1;

    float accA[4], accB[4];
#pragma unroll
    for (int j = 0; j < 4; j++) { accA[j] = b1[ca]; accB[j] = b1[cb]; }

    float wa[EMB], wb[EMB];

    // ---- phase 1: bn2(conv) with W1[:, 0:64] ----
#pragma unroll
    for (int i = 0; i < 8; i++) {
        int idx = t + i * 256;
        int r = idx >> 6, c = idx & 63;
        int gr = row0 + r;
        float v = (gr < nrows) ? conv[gr * EMB + c] : 0.f;
        xs[r][c] = v * d_sc[128 + c] + d_sc[192 + c];
    }
#pragma unroll
    for (int k = 0; k < EMB; k++) {
        wa[k] = W1[ca * 128 + k];
        wb[k] = W1[cb * 128 + k];
    }
    __syncthreads();
#pragma unroll
    for (int k2 = 0; k2 < 32; k2++) {
#pragma unroll
        for (int j = 0; j < 4; j++) {
            float2 x2 = *(const float2*)&xs[rg * 4 + j][2 * k2];
            accA[j] = fmaf(x2.x, wa[2 * k2], accA[j]);
            accA[j] = fmaf(x2.y, wa[2 * k2 + 1], accA[j]);
            accB[j] = fmaf(x2.x, wb[2 * k2], accB[j]);
            accB[j] = fmaf(x2.y, wb[2 * k2 + 1], accB[j]);
        }
    }
    __syncthreads();

    // ---- phase 2: right with W1[:, 64:128] ----
#pragma unroll
    for (int i = 0; i < 8; i++) {
        int idx = t + i * 256;
        int r = idx >> 6, c = idx & 63;
        int gr = row0 + r;
        xs[r][c] = (gr < nrows) ? right[gr * EMB + c] : 0.f;
    }
#pragma unroll
    for (int k = 0; k < EMB; k++) {
        wa[k] = W1[ca * 128 + 64 + k];
        wb[k] = W1[cb * 128 + 64 + k];
    }
    __syncthreads();
#pragma unroll
    for (int k2 = 0; k2 < 32; k2++) {
#pragma unroll
        for (int j = 0; j < 4; j++) {
            float2 x2 = *(const float2*)&xs[rg * 4 + j][2 * k2];
            accA[j] = fmaf(x2.x, wa[2 * k2], accA[j]);
            accA[j] = fmaf(x2.y, wa[2 * k2 + 1], accA[j]);
            accB[j] = fmaf(x2.x, wb[2 * k2], accB[j]);
            accB[j] = fmaf(x2.y, wb[2 * k2 + 1], accB[j]);
        }
    }

#pragma unroll
    for (int j = 0; j < 4; j++) {
        int gr = row0 + rg * 4 + j;
        if (gr < nrows) {
            float a = fmaxf(accA[j], 0.f);
            float b = fmaxf(accB[j], 0.f);
            ((float2*)out)[gr * 32 + cg] = make_float2(a, b);
        }
    }
}

// ---------------- launch -----------------------------------------------------
extern "C" void kernel_launch(void* const* d_in, const int* in_sizes, int n_in,
                              void* d_out, int out_size)
{
    (void)n_in; (void)out_size;
    const float* left   = (const float*)d_in[0];
    const int*   ei     = (const int*)d_in[1];
    const float* ef     = (const float*)d_in[2];
    const float* right  = (const float*)d_in[3];
    const float* W_left  = (const float*)d_in[5];
    const float* b_left  = (const float*)d_in[6];
    const float* W_edge  = (const float*)d_in[7];
    const float* W_right = (const float*)d_in[8];
    const float* g1      = (const float*)d_in[9];
    const float* bt1     = (const float*)d_in[10];
    const float* W_final = (const float*)d_in[11];
    const float* b_final = (const float*)d_in[12];
    const float* g2      = (const float*)d_in[13];
    const float* bt2     = (const float*)d_in[14];
    const float* W1      = (const float*)d_in[15];
    const float* b1      = (const float*)d_in[16];
    const float* W2      = (const float*)d_in[17];
    const float* b2      = (const float*)d_in[18];
    float* out = (float*)d_out;

    int NL = in_sizes[0] / EMB;
    int NE = in_sizes[2];
    int NR = in_sizes[3] / EMB;

    float *pLP, *pRP, *pS, *pConv, *pH, *pDeg;
    cudaGetSymbolAddress((void**)&pLP, d_LP);
    cudaGetSymbolAddress((void**)&pRP, d_RP);
    cudaGetSymbolAddress((void**)&pS, d_S);
    cudaGetSymbolAddress((void**)&pConv, d_conv);
    cudaGetSymbolAddress((void**)&pH, d_h);
    cudaGetSymbolAddress((void**)&pDeg, d_deg);

    // 1. zero atomically-accumulated scratch
    zero_kernel<<<(NR * EMB + 255) / 256, 256>>>(NR * EMB, NR);
    // 2. projections
    gemm64_kernel<1><<<(NL + 31) / 32, 256>>>(left, W_left, b_left, nullptr, pLP, NL);
    gemm64_kernel<0><<<(NR + 31) / 32, 256>>>(right, W_right, nullptr, nullptr, pRP, NR);
    // 3. edge pass 1: bn1 stats + degree
    edge_stats_kernel<<<1184, 256>>>(ei, ef, W_edge, NE);
    // 4. bn1 finalize
    bn_finalize_kernel<<<1, 64>>>(g1, bt1, (float)NE, 0, 0);
    // 5. edge pass 2: recompute joint, bn1+relu, scatter-add into S
    edge_scatter_kernel<<<(NE * 16 + 255) / 256, 256>>>(ei, ef, W_edge, NE);
    // 6. conv = S @ W_final.T + deg*b_final ; accumulate bn2 stats
    gemm64_kernel<2><<<(NR + 31) / 32, 256>>>(pS, W_final, b_final, pDeg, pConv, NR);
    // 7. bn2 finalize
    bn_finalize_kernel<<<1, 64>>>(g2, bt2, (float)NR, 128, 128);
    // 8. h = relu([bn2(conv), right] @ W1.T + b1)
    out1_kernel<<<(NR + 31) / 32, 256>>>(pConv, right, W1, b1, pH, NR);
    // 9. out = relu(h @ W2.T + b2)
    gemm64_kernel<3><<<(NR + 31) / 32, 256>>>(pH, W2, b2, nullptr, out, NR);
}

// round 4
// speedup vs baseline: 7.5059x; 7.5059x over previous
#include <cuda_runtime.h>

#define EMB 64
#define NL_MAX 50000
#define NR_MAX 100000
#define NE_MAX 1000000
#define BN_EPS 1e-5f

#define WPAD 66         // wsT row pad: bank = (2k + c) % 32, conflict-free float2 reads
#define TROWS 96        // rows per block tile in gemm64 / out1
#define RPT 12          // rows per thread (TROWS / 8 warps)

// ---------------- scratch (static device globals; no runtime alloc) ----------
__device__ float d_LP[NL_MAX * EMB];
__device__ float d_RP[NR_MAX * EMB];
__device__ float d_S[NR_MAX * EMB];
__device__ float d_conv[NR_MAX * EMB];
__device__ float d_h[NR_MAX * EMB];
__device__ float d_deg[NR_MAX];
__device__ float d_stats[256];   // [0:64) sum1, [64:128) sq1, [128:192) sum2, [192:256) sq2
__device__ float d_sc[256];      // [0:64) scale1, [64:128) shift1, [128:192) scale2, [192:256) shift2

// ---------------- zero scratch that is atomically accumulated ---------------
__global__ void zero_kernel(int nS, int nR) {
    int i = blockIdx.x * blockDim.x + threadIdx.x;
    if (i < nS) d_S[i] = 0.f;
    if (i < nR) d_deg[i] = 0.f;
    if (i < 256) d_stats[i] = 0.f;
}

// ---------------- generic 64-wide GEMM: out = f(X @ W.T (+bias terms)) ------
// MODE 0: out = X@W.T
// MODE 1: out = X@W.T + bias
// MODE 2: out = X@W.T + deg*bias ; accumulate column sum/sumsq -> d_stats[128..]
// MODE 3: out = relu(X@W.T + bias)
// 256 threads. cg=t&31 owns cols (2cg, 2cg+1); rg=t>>5 owns rows rg*12..+11.
// W staged coalesced into shared (transposed, pad 66); x tile read by broadcast.
template <int MODE>
__global__ __launch_bounds__(256) void gemm64_kernel(
    const float* __restrict__ X, const float* __restrict__ W,
    const float* __restrict__ bias, const float* __restrict__ deg,
    float* __restrict__ out, int nrows)
{
    __shared__ float xs[TROWS][EMB];
    __shared__ float wsT[EMB][WPAD];
    __shared__ float red[128];

    int t = threadIdx.x;
    int cg = t & 31;
    int rg = t >> 5;
    int row0 = blockIdx.x * TROWS;
    int ca = 2 * cg, cb = 2 * cg + 1;
    int r0 = rg * RPT;

    // stage W -> shared, coalesced float4 reads, transposed scatter writes
#pragma unroll
    for (int p = 0; p < 4; p++) {
        int i = t + p * 256;            // 0..1023 float4 index
        int c = i >> 4;                 // 0..63
        int k4 = (i & 15) * 4;
        float4 w4 = *(const float4*)&W[c * EMB + k4];
        wsT[k4 + 0][c] = w4.x;
        wsT[k4 + 1][c] = w4.y;
        wsT[k4 + 2][c] = w4.z;
        wsT[k4 + 3][c] = w4.w;
    }
    // stage x tile, coalesced float4 (TROWS*16 = 1536 float4 / 256 thr = 6 each)
#pragma unroll
    for (int p = 0; p < TROWS / 16; p++) {
        int i = t + p * 256;
        int r = i >> 4;
        int c4 = (i & 15) * 4;
        int gr = row0 + r;
        float4 v = (gr < nrows) ? *(const float4*)&X[gr * EMB + c4]
                                : make_float4(0.f, 0.f, 0.f, 0.f);
        *(float4*)&xs[r][c4] = v;
    }
    __syncthreads();

    float accA[RPT], accB[RPT];
    float bca = 0.f, bcb = 0.f;
    if (MODE == 1 || MODE == 3 || MODE == 2) { bca = bias[ca]; bcb = bias[cb]; }
#pragma unroll
    for (int j = 0; j < RPT; j++) {
        if (MODE == 1 || MODE == 3) {
            accA[j] = bca; accB[j] = bcb;
        } else if (MODE == 2) {
            int gr = row0 + r0 + j;
            float dv = (gr < nrows) ? deg[gr] : 0.f;
            accA[j] = dv * bca; accB[j] = dv * bcb;
        } else {
            accA[j] = 0.f; accB[j] = 0.f;
        }
    }

#pragma unroll
    for (int k2 = 0; k2 < 32; k2++) {
        int k = 2 * k2;
        float2 w0 = *(const float2*)&wsT[k][ca];      // (wa[k], wb[k])
        float2 w1 = *(const float2*)&wsT[k + 1][ca];  // (wa[k+1], wb[k+1])
#pragma unroll
        for (int j = 0; j < RPT; j++) {
            float2 x2 = *(const float2*)&xs[r0 + j][k];   // broadcast
            accA[j] = fmaf(x2.x, w0.x, accA[j]);
            accA[j] = fmaf(x2.y, w1.x, accA[j]);
            accB[j] = fmaf(x2.x, w0.y, accB[j]);
            accB[j] = fmaf(x2.y, w1.y, accB[j]);
        }
    }

    float sA = 0.f, qA = 0.f, sB = 0.f, qB = 0.f;
#pragma unroll
    for (int j = 0; j < RPT; j++) {
        int gr = row0 + r0 + j;
        if (gr < nrows) {
            float a = accA[j], b = accB[j];
            if (MODE == 3) { a = fmaxf(a, 0.f); b = fmaxf(b, 0.f); }
            ((float2*)out)[gr * 32 + cg] = make_float2(a, b);
            if (MODE == 2) { sA += a; qA += a * a; sB += b; qB += b * b; }
        }
    }

    if (MODE == 2) {
        if (t < 128) red[t] = 0.f;
        __syncthreads();
        atomicAdd(&red[ca], sA);
        atomicAdd(&red[64 + ca], qA);
        atomicAdd(&red[cb], sB);
        atomicAdd(&red[64 + cb], qB);
        __syncthreads();
        if (t < 128) atomicAdd(&d_stats[128 + t], red[t]);
    }
}

// ---------------- edge pass 1: bn1 column sums/sumsq + degree ---------------
__global__ __launch_bounds__(256) void edge_stats_kernel(
    const int* __restrict__ ei, const float* __restrict__ ef,
    const float* __restrict__ Wedge, int NE)
{
    int t = threadIdx.x;
    int g = t & 15;
    float4 we = ((const float4*)Wedge)[g];
    float4 sum = make_float4(0.f, 0.f, 0.f, 0.f);
    float4 sq = make_float4(0.f, 0.f, 0.f, 0.f);

    for (int e = blockIdx.x * 16 + (t >> 4); e < NE; e += gridDim.x * 16) {
        int i0 = ei[e];
        int i1 = ei[NE + e];
        float f = ef[e];
        float4 lp = ((const float4*)d_LP)[i0 * 16 + g];
        float4 rp = ((const float4*)d_RP)[i1 * 16 + g];
        float4 j;
        j.x = fmaf(f, we.x, lp.x + rp.x);
        j.y = fmaf(f, we.y, lp.y + rp.y);
        j.z = fmaf(f, we.z, lp.z + rp.z);
        j.w = fmaf(f, we.w, lp.w + rp.w);
        sum.x += j.x; sum.y += j.y; sum.z += j.z; sum.w += j.w;
        sq.x += j.x * j.x; sq.y += j.y * j.y; sq.z += j.z * j.z; sq.w += j.w * j.w;
        if (g == 0) atomicAdd(&d_deg[i1], 1.f);
    }

    __shared__ float red[128];
    if (t < 128) red[t] = 0.f;
    __syncthreads();
    atomicAdd(&red[4 * g + 0], sum.x);
    atomicAdd(&red[4 * g + 1], sum.y);
    atomicAdd(&red[4 * g + 2], sum.z);
    atomicAdd(&red[4 * g + 3], sum.w);
    atomicAdd(&red[64 + 4 * g + 0], sq.x);
    atomicAdd(&red[64 + 4 * g + 1], sq.y);
    atomicAdd(&red[64 + 4 * g + 2], sq.z);
    atomicAdd(&red[64 + 4 * g + 3], sq.w);
    __syncthreads();
    if (t < 128) atomicAdd(&d_stats[t], red[t]);
}

// ---------------- batchnorm finalize: stats -> scale/shift ------------------
__global__ void bn_finalize_kernel(const float* __restrict__ gamma,
                                   const float* __restrict__ beta,
                                   float cnt, int soff, int ooff)
{
    int c = threadIdx.x;
    if (c < 64) {
        float mean = d_stats[soff + c] / cnt;
        float var = d_stats[soff + 64 + c] / cnt - mean * mean;
        float sc = gamma[c] * rsqrtf(var + BN_EPS);
        d_sc[ooff + c] = sc;
        d_sc[ooff + 64 + c] = beta[c] - mean * sc;
    }
}

// ---------------- edge pass 2: recompute joint, bn1+relu, scatter into S ----
__global__ __launch_bounds__(256) void edge_scatter_kernel(
    const int* __restrict__ ei, const float* __restrict__ ef,
    const float* __restrict__ Wedge, int NE)
{
    int tid = blockIdx.x * 256 + threadIdx.x;
    int e = tid >> 4;
    int g = tid & 15;
    if (e >= NE) return;

    float4 we = ((const float4*)Wedge)[g];
    float4 s = ((const float4*)d_sc)[g];
    float4 sh = ((const float4*)d_sc)[16 + g];

    int i0 = ei[e];
    int i1 = ei[NE + e];
    float f = ef[e];
    float4 lp = ((const float4*)d_LP)[i0 * 16 + g];
    float4 rp = ((const float4*)d_RP)[i1 * 16 + g];

    float4 v;
    v.x = fmaxf(fmaf(fmaf(f, we.x, lp.x + rp.x), s.x, sh.x), 0.f);
    v.y = fmaxf(fmaf(fmaf(f, we.y, lp.y + rp.y), s.y, sh.y), 0.f);
    v.z = fmaxf(fmaf(fmaf(f, we.z, lp.z + rp.z), s.z, sh.z), 0.f);
    v.w = fmaxf(fmaf(fmaf(f, we.w, lp.w + rp.w), s.w, sh.w), 0.f);

    float* p = &d_S[i1 * EMB + 4 * g];
    asm volatile("red.global.add.v4.f32 [%0], {%1,%2,%3,%4};"
                 :: "l"(p), "f"(v.x), "f"(v.y), "f"(v.z), "f"(v.w) : "memory");
}

// ---------------- output layer 1: h = relu([bn2(conv), right] @ W1.T + b1) --
// Same structure as gemm64 but K=128 processed in two 64-wide phases
// (phase 1: bn2(conv), phase 2: right), reloading wsT between phases.
__global__ __launch_bounds__(256) void out1_kernel(
    const float* __restrict__ conv, const float* __restrict__ right,
    const float* __restrict__ W1, const float* __restrict__ b1,
    float* __restrict__ out, int nrows)
{
    __shared__ float xs[TROWS][EMB];
    __shared__ float wsT[EMB][WPAD];

    int t = threadIdx.x;
    int cg = t & 31;
    int rg = t >> 5;
    int row0 = blockIdx.x * TROWS;
    int ca = 2 * cg, cb = 2 * cg + 1;
    int r0 = rg * RPT;

    float accA[RPT], accB[RPT];
    float bca = b1[ca], bcb = b1[cb];
#pragma unroll
    for (int j = 0; j < RPT; j++) { accA[j] = bca; accB[j] = bcb; }

#pragma unroll
    for (int phase = 0; phase < 2; phase++) {
        int koff = phase * 64;
        // stage W1[:, koff:koff+64] transposed
#pragma unroll
        for (int p = 0; p < 4; p++) {
            int i = t + p * 256;
            int c = i >> 4;
            int k4 = (i & 15) * 4;
            float4 w4 = *(const float4*)&W1[c * 128 + koff + k4];
            wsT[k4 + 0][c] = w4.x;
            wsT[k4 + 1][c] = w4.y;
            wsT[k4 + 2][c] = w4.z;
            wsT[k4 + 3][c] = w4.w;
        }
        // stage x tile
#pragma unroll
        for (int p = 0; p < TROWS / 16; p++) {
            int i = t + p * 256;
            int r = i >> 4;
            int c4 = (i & 15) * 4;
            int gr = row0 + r;
            float4 v;
            if (gr < nrows) {
                if (phase == 0) {
                    v = *(const float4*)&conv[gr * EMB + c4];
                    v.x = v.x * d_sc[128 + c4 + 0] + d_sc[192 + c4 + 0];
                    v.y = v.y * d_sc[128 + c4 + 1] + d_sc[192 + c4 + 1];
                    v.z = v.z * d_sc[128 + c4 + 2] + d_sc[192 + c4 + 2];
                    v.w = v.w * d_sc[128 + c4 + 3] + d_sc[192 + c4 + 3];
                } else {
                    v = *(const float4*)&right[gr * EMB + c4];
                }
            } else {
                v = make_float4(0.f, 0.f, 0.f, 0.f);
            }
            *(float4*)&xs[r][c4] = v;
        }
        __syncthreads();

#pragma unroll
        for (int k2 = 0; k2 < 32; k2++) {
            int k = 2 * k2;
            float2 w0 = *(const float2*)&wsT[k][ca];
            float2 w1 = *(const float2*)&wsT[k + 1][ca];
#pragma unroll
            for (int j = 0; j < RPT; j++) {
                float2 x2 = *(const float2*)&xs[r0 + j][k];
                accA[j] = fmaf(x2.x, w0.x, accA[j]);
                accA[j] = fmaf(x2.y, w1.x, accA[j]);
                accB[j] = fmaf(x2.x, w0.y, accB[j]);
                accB[j] = fmaf(x2.y, w1.y, accB[j]);
            }
        }
        __syncthreads();
    }

#pragma unroll
    for (int j = 0; j < RPT; j++) {
        int gr = row0 + r0 + j;
        if (gr < nrows) {
            float a = fmaxf(accA[j], 0.f);
            float b = fmaxf(accB[j], 0.f);
            ((float2*)out)[gr * 32 + cg] = make_float2(a, b);
        }
    }
}

// ---------------- launch -----------------------------------------------------
extern "C" void kernel_launch(void* const* d_in, const int* in_sizes, int n_in,
                              void* d_out, int out_size)
{
    (void)n_in; (void)out_size;
    const float* left   = (const float*)d_in[0];
    const int*   ei     = (const int*)d_in[1];
    const float* ef     = (const float*)d_in[2];
    const float* right  = (const float*)d_in[3];
    const float* W_left  = (const float*)d_in[5];
    const float* b_left  = (const float*)d_in[6];
    const float* W_edge  = (const float*)d_in[7];
    const float* W_right = (const float*)d_in[8];
    const float* g1      = (const float*)d_in[9];
    const float* bt1     = (const float*)d_in[10];
    const float* W_final = (const float*)d_in[11];
    const float* b_final = (const float*)d_in[12];
    const float* g2      = (const float*)d_in[13];
    const float* bt2     = (const float*)d_in[14];
    const float* W1      = (const float*)d_in[15];
    const float* b1      = (const float*)d_in[16];
    const float* W2      = (const float*)d_in[17];
    const float* b2      = (const float*)d_in[18];
    float* out = (float*)d_out;

    int NL = in_sizes[0] / EMB;
    int NE = in_sizes[2];
    int NR = in_sizes[3] / EMB;

    float *pLP, *pRP, *pS, *pConv, *pH, *pDeg;
    cudaGetSymbolAddress((void**)&pLP, d_LP);
    cudaGetSymbolAddress((void**)&pRP, d_RP);
    cudaGetSymbolAddress((void**)&pS, d_S);
    cudaGetSymbolAddress((void**)&pConv, d_conv);
    cudaGetSymbolAddress((void**)&pH, d_h);
    cudaGetSymbolAddress((void**)&pDeg, d_deg);

    // 1. zero atomically-accumulated scratch
    zero_kernel<<<(NR * EMB + 255) / 256, 256>>>(NR * EMB, NR);
    // 2. projections
    gemm64_kernel<1><<<(NL + TROWS - 1) / TROWS, 256>>>(left, W_left, b_left, nullptr, pLP, NL);
    gemm64_kernel<0><<<(NR + TROWS - 1) / TROWS, 256>>>(right, W_right, nullptr, nullptr, pRP, NR);
    // 3. edge pass 1: bn1 stats + degree
    edge_stats_kernel<<<1184, 256>>>(ei, ef, W_edge, NE);
    // 4. bn1 finalize
    bn_finalize_kernel<<<1, 64>>>(g1, bt1, (float)NE, 0, 0);
    // 5. edge pass 2: recompute joint, bn1+relu, scatter-add into S
    edge_scatter_kernel<<<(NE * 16 + 255) / 256, 256>>>(ei, ef, W_edge, NE);
    // 6. conv = S @ W_final.T + deg*b_final ; accumulate bn2 stats
    gemm64_kernel<2><<<(NR + TROWS - 1) / TROWS, 256>>>(pS, W_final, b_final, pDeg, pConv, NR);
    // 7. bn2 finalize
    bn_finalize_kernel<<<1, 64>>>(g2, bt2, (float)NR, 128, 128);
    // 8. h = relu([bn2(conv), right] @ W1.T + b1)
    out1_kernel<<<(NR + TROWS - 1) / TROWS, 256>>>(pConv, right, W1, b1, pH, NR);
    // 9. out = relu(h @ W2.T + b2)
    gemm64_kernel<3><<<(NR + TROWS - 1) / TROWS, 256>>>(pH, W2, b2, nullptr, out, NR);
}

// round 5
// speedup vs baseline: 7.9263x; 1.0560x over previous
#include <cuda_runtime.h>

#define EMB 64
#define NL_MAX 50000
#define NR_MAX 100000
#define NE_MAX 1000000
#define BN_EPS 1e-5f

#define WPAD 66         // wsT row pad: conflict-free float2 reads
#define TROWS 96        // rows per block tile
#define RPT 12          // rows per thread (TROWS / 8 warps)

// ---------------- scratch (static device globals) ----------------------------
__device__ float d_LP[NL_MAX * EMB];
__device__ float d_RP[NR_MAX * EMB];
__device__ float d_S[NR_MAX * EMB];
__device__ float d_conv[NR_MAX * EMB];
__device__ float d_deg[NR_MAX];
__device__ float d_stats[256];   // [0:64) sum1, [64:128) sq1, [128:192) sum2, [192:256) sq2
__device__ float d_sc[256];      // [0:64) scale1, [64:128) shift1, [128:192) scale2, [192:256) shift2

// ---------------- zero scratch (vectorized) ----------------------------------
__global__ void zero_kernel(int nS4, int nR) {
    int i = blockIdx.x * blockDim.x + threadIdx.x;
    if (i < nS4) ((float4*)d_S)[i] = make_float4(0.f, 0.f, 0.f, 0.f);
    if (i < nR) d_deg[i] = 0.f;
    if (i < 256) d_stats[i] = 0.f;
}

// ---------------- generic 64-wide GEMM --------------------------------------
// MODE 0: out = X@W.T ; 1: +bias ; 2: +deg*bias & bn2 stats ; 3: relu(+bias)
template <int MODE>
__global__ __launch_bounds__(256) void gemm64_kernel(
    const float* __restrict__ X, const float* __restrict__ W,
    const float* __restrict__ bias, const float* __restrict__ deg,
    float* __restrict__ out, int nrows)
{
    __shared__ float xs[TROWS][EMB];
    __shared__ float wsT[EMB][WPAD];
    __shared__ float red[128];

    int t = threadIdx.x;
    int cg = t & 31;
    int rg = t >> 5;
    int row0 = blockIdx.x * TROWS;
    int ca = 2 * cg, cb = 2 * cg + 1;
    int r0 = rg * RPT;

#pragma unroll
    for (int p = 0; p < 4; p++) {
        int i = t + p * 256;
        int c = i >> 4;
        int k4 = (i & 15) * 4;
        float4 w4 = *(const float4*)&W[c * EMB + k4];
        wsT[k4 + 0][c] = w4.x;
        wsT[k4 + 1][c] = w4.y;
        wsT[k4 + 2][c] = w4.z;
        wsT[k4 + 3][c] = w4.w;
    }
#pragma unroll
    for (int p = 0; p < TROWS / 16; p++) {
        int i = t + p * 256;
        int r = i >> 4;
        int c4 = (i & 15) * 4;
        int gr = row0 + r;
        float4 v = (gr < nrows) ? *(const float4*)&X[gr * EMB + c4]
                                : make_float4(0.f, 0.f, 0.f, 0.f);
        *(float4*)&xs[r][c4] = v;
    }
    __syncthreads();

    float accA[RPT], accB[RPT];
    float bca = 0.f, bcb = 0.f;
    if (MODE != 0) { bca = bias[ca]; bcb = bias[cb]; }
#pragma unroll
    for (int j = 0; j < RPT; j++) {
        if (MODE == 1 || MODE == 3) {
            accA[j] = bca; accB[j] = bcb;
        } else if (MODE == 2) {
            int gr = row0 + r0 + j;
            float dv = (gr < nrows) ? deg[gr] : 0.f;
            accA[j] = dv * bca; accB[j] = dv * bcb;
        } else {
            accA[j] = 0.f; accB[j] = 0.f;
        }
    }

#pragma unroll
    for (int k2 = 0; k2 < 32; k2++) {
        int k = 2 * k2;
        float2 w0 = *(const float2*)&wsT[k][ca];
        float2 w1 = *(const float2*)&wsT[k + 1][ca];
#pragma unroll
        for (int j = 0; j < RPT; j++) {
            float2 x2 = *(const float2*)&xs[r0 + j][k];
            accA[j] = fmaf(x2.x, w0.x, accA[j]);
            accA[j] = fmaf(x2.y, w1.x, accA[j]);
            accB[j] = fmaf(x2.x, w0.y, accB[j]);
            accB[j] = fmaf(x2.y, w1.y, accB[j]);
        }
    }

    float sA = 0.f, qA = 0.f, sB = 0.f, qB = 0.f;
#pragma unroll
    for (int j = 0; j < RPT; j++) {
        int gr = row0 + r0 + j;
        if (gr < nrows) {
            float a = accA[j], b = accB[j];
            if (MODE == 3) { a = fmaxf(a, 0.f); b = fmaxf(b, 0.f); }
            ((float2*)out)[gr * 32 + cg] = make_float2(a, b);
            if (MODE == 2) { sA += a; qA += a * a; sB += b; qB += b * b; }
        }
    }

    if (MODE == 2) {
        if (t < 128) red[t] = 0.f;
        __syncthreads();
        atomicAdd(&red[ca], sA);
        atomicAdd(&red[64 + ca], qA);
        atomicAdd(&red[cb], sB);
        atomicAdd(&red[64 + cb], qB);
        __syncthreads();
        if (t < 128) atomicAdd(&d_stats[128 + t], red[t]);
    }
}

// ---------------- edge pass 1: bn1 stats + degree (ILP x2) ------------------
__global__ __launch_bounds__(256) void edge_stats_kernel(
    const int* __restrict__ ei, const float* __restrict__ ef,
    const float* __restrict__ Wedge, int NE)
{
    int t = threadIdx.x;
    int g = t & 15;
    int slot = blockIdx.x * 16 + (t >> 4);
    int step = gridDim.x * 16;
    float4 we = ((const float4*)Wedge)[g];
    float4 sum = make_float4(0.f, 0.f, 0.f, 0.f);
    float4 sq = make_float4(0.f, 0.f, 0.f, 0.f);

    for (int e = slot; e < NE; e += 2 * step) {
        int eB = e + step;
        bool hasB = eB < NE;
        int eBc = hasB ? eB : e;
        // independent front-batched loads (MLP ~ 10)
        int i0a = ei[e];
        int i1a = ei[NE + e];
        float fa = ef[e];
        int i0b = ei[eBc];
        int i1b = ei[NE + eBc];
        float fb = ef[eBc];
        float4 lpA = ((const float4*)d_LP)[i0a * 16 + g];
        float4 rpA = ((const float4*)d_RP)[i1a * 16 + g];
        float4 lpB = ((const float4*)d_LP)[i0b * 16 + g];
        float4 rpB = ((const float4*)d_RP)[i1b * 16 + g];

        float4 jA;
        jA.x = fmaf(fa, we.x, lpA.x + rpA.x);
        jA.y = fmaf(fa, we.y, lpA.y + rpA.y);
        jA.z = fmaf(fa, we.z, lpA.z + rpA.z);
        jA.w = fmaf(fa, we.w, lpA.w + rpA.w);
        sum.x += jA.x; sum.y += jA.y; sum.z += jA.z; sum.w += jA.w;
        sq.x += jA.x * jA.x; sq.y += jA.y * jA.y;
        sq.z += jA.z * jA.z; sq.w += jA.w * jA.w;

        float m = hasB ? 1.f : 0.f;
        float4 jB;
        jB.x = fmaf(fb, we.x, lpB.x + rpB.x);
        jB.y = fmaf(fb, we.y, lpB.y + rpB.y);
        jB.z = fmaf(fb, we.z, lpB.z + rpB.z);
        jB.w = fmaf(fb, we.w, lpB.w + rpB.w);
        sum.x += m * jB.x; sum.y += m * jB.y;
        sum.z += m * jB.z; sum.w += m * jB.w;
        sq.x += m * jB.x * jB.x; sq.y += m * jB.y * jB.y;
        sq.z += m * jB.z * jB.z; sq.w += m * jB.w * jB.w;

        if (g == 0) {
            atomicAdd(&d_deg[i1a], 1.f);
            if (hasB) atomicAdd(&d_deg[i1b], 1.f);
        }
    }

    __shared__ float red[128];
    if (t < 128) red[t] = 0.f;
    __syncthreads();
    atomicAdd(&red[4 * g + 0], sum.x);
    atomicAdd(&red[4 * g + 1], sum.y);
    atomicAdd(&red[4 * g + 2], sum.z);
    atomicAdd(&red[4 * g + 3], sum.w);
    atomicAdd(&red[64 + 4 * g + 0], sq.x);
    atomicAdd(&red[64 + 4 * g + 1], sq.y);
    atomicAdd(&red[64 + 4 * g + 2], sq.z);
    atomicAdd(&red[64 + 4 * g + 3], sq.w);
    __syncthreads();
    if (t < 128) atomicAdd(&d_stats[t], red[t]);
}

// ---------------- batchnorm finalize ----------------------------------------
__global__ void bn_finalize_kernel(const float* __restrict__ gamma,
                                   const float* __restrict__ beta,
                                   float cnt, int soff, int ooff)
{
    int c = threadIdx.x;
    if (c < 64) {
        float mean = d_stats[soff + c] / cnt;
        float var = d_stats[soff + 64 + c] / cnt - mean * mean;
        float sc = gamma[c] * rsqrtf(var + BN_EPS);
        d_sc[ooff + c] = sc;
        d_sc[ooff + 64 + c] = beta[c] - mean * sc;
    }
}

// ---------------- edge pass 2: bn1+relu joint, scatter into S (ILP x2) ------
__global__ __launch_bounds__(256) void edge_scatter_kernel(
    const int* __restrict__ ei, const float* __restrict__ ef,
    const float* __restrict__ Wedge, int NE)
{
    int tid = blockIdx.x * 256 + threadIdx.x;
    int p = tid >> 4;
    int g = tid & 15;
    int eA = 2 * p;
    if (eA >= NE) return;
    int eB = eA + 1;
    bool hasB = eB < NE;
    int eBc = hasB ? eB : eA;

    float4 we = ((const float4*)Wedge)[g];
    float4 s = ((const float4*)d_sc)[g];
    float4 sh = ((const float4*)d_sc)[16 + g];

    // independent front-batched loads
    int i0a = ei[eA];
    int i1a = ei[NE + eA];
    float fa = ef[eA];
    int i0b = ei[eBc];
    int i1b = ei[NE + eBc];
    float fb = ef[eBc];
    float4 lpA = ((const float4*)d_LP)[i0a * 16 + g];
    float4 rpA = ((const float4*)d_RP)[i1a * 16 + g];
    float4 lpB = ((const float4*)d_LP)[i0b * 16 + g];
    float4 rpB = ((const float4*)d_RP)[i1b * 16 + g];

    float4 vA;
    vA.x = fmaxf(fmaf(fmaf(fa, we.x, lpA.x + rpA.x), s.x, sh.x), 0.f);
    vA.y = fmaxf(fmaf(fmaf(fa, we.y, lpA.y + rpA.y), s.y, sh.y), 0.f);
    vA.z = fmaxf(fmaf(fmaf(fa, we.z, lpA.z + rpA.z), s.z, sh.z), 0.f);
    vA.w = fmaxf(fmaf(fmaf(fa, we.w, lpA.w + rpA.w), s.w, sh.w), 0.f);
    float* pa = &d_S[i1a * EMB + 4 * g];
    asm volatile("red.global.add.v4.f32 [%0], {%1,%2,%3,%4};"
                 :: "l"(pa), "f"(vA.x), "f"(vA.y), "f"(vA.z), "f"(vA.w) : "memory");

    if (hasB) {
        float4 vB;
        vB.x = fmaxf(fmaf(fmaf(fb, we.x, lpB.x + rpB.x), s.x, sh.x), 0.f);
        vB.y = fmaxf(fmaf(fmaf(fb, we.y, lpB.y + rpB.y), s.y, sh.y), 0.f);
        vB.z = fmaxf(fmaf(fmaf(fb, we.z, lpB.z + rpB.z), s.z, sh.z), 0.f);
        vB.w = fmaxf(fmaf(fmaf(fb, we.w, lpB.w + rpB.w), s.w, sh.w), 0.f);
        float* pb = &d_S[i1b * EMB + 4 * g];
        asm volatile("red.global.add.v4.f32 [%0], {%1,%2,%3,%4};"
                     :: "l"(pb), "f"(vB.x), "f"(vB.y), "f"(vB.z), "f"(vB.w) : "memory");
    }
}

// ---------------- fused output: h = relu([bn2(conv), right]@W1.T + b1);
//                  out = relu(h @ W2.T + b2) ---------------------------------
__global__ __launch_bounds__(256) void out_fused_kernel(
    const float* __restrict__ conv, const float* __restrict__ right,
    const float* __restrict__ W1, const float* __restrict__ b1,
    const float* __restrict__ W2, const float* __restrict__ b2,
    float* __restrict__ out, int nrows)
{
    __shared__ float xs[TROWS][EMB];
    __shared__ float wsT[EMB][WPAD];

    int t = threadIdx.x;
    int cg = t & 31;
    int rg = t >> 5;
    int row0 = blockIdx.x * TROWS;
    int ca = 2 * cg, cb = 2 * cg + 1;
    int r0 = rg * RPT;

    float accA[RPT], accB[RPT];
    float bca = b1[ca], bcb = b1[cb];
#pragma unroll
    for (int j = 0; j < RPT; j++) { accA[j] = bca; accB[j] = bcb; }

#pragma unroll
    for (int phase = 0; phase < 2; phase++) {
        int koff = phase * 64;
#pragma unroll
        for (int p = 0; p < 4; p++) {
            int i = t + p * 256;
            int c = i >> 4;
            int k4 = (i & 15) * 4;
            float4 w4 = *(const float4*)&W1[c * 128 + koff + k4];
            wsT[k4 + 0][c] = w4.x;
            wsT[k4 + 1][c] = w4.y;
            wsT[k4 + 2][c] = w4.z;
            wsT[k4 + 3][c] = w4.w;
        }
#pragma unroll
        for (int p = 0; p < TROWS / 16; p++) {
            int i = t + p * 256;
            int r = i >> 4;
            int c4 = (i & 15) * 4;
            int gr = row0 + r;
            float4 v;
            if (gr < nrows) {
                if (phase == 0) {
                    v = *(const float4*)&conv[gr * EMB + c4];
                    v.x = v.x * d_sc[128 + c4 + 0] + d_sc[192 + c4 + 0];
                    v.y = v.y * d_sc[128 + c4 + 1] + d_sc[192 + c4 + 1];
                    v.z = v.z * d_sc[128 + c4 + 2] + d_sc[192 + c4 + 2];
                    v.w = v.w * d_sc[128 + c4 + 3] + d_sc[192 + c4 + 3];
                } else {
                    v = *(const float4*)&right[gr * EMB + c4];
                }
            } else {
                v = make_float4(0.f, 0.f, 0.f, 0.f);
            }
            *(float4*)&xs[r][c4] = v;
        }
        __syncthreads();

#pragma unroll
        for (int k2 = 0; k2 < 32; k2++) {
            int k = 2 * k2;
            float2 w0 = *(const float2*)&wsT[k][ca];
            float2 w1 = *(const float2*)&wsT[k + 1][ca];
#pragma unroll
            for (int j = 0; j < RPT; j++) {
                float2 x2 = *(const float2*)&xs[r0 + j][k];
                accA[j] = fmaf(x2.x, w0.x, accA[j]);
                accA[j] = fmaf(x2.y, w1.x, accA[j]);
                accB[j] = fmaf(x2.x, w0.y, accB[j]);
                accB[j] = fmaf(x2.y, w1.y, accB[j]);
            }
        }
        __syncthreads();
    }

    // h -> shared (relu); stage W2; second GEMM in-block
#pragma unroll
    for (int j = 0; j < RPT; j++) {
        float a = fmaxf(accA[j], 0.f);
        float b = fmaxf(accB[j], 0.f);
        *(float2*)&xs[r0 + j][ca] = make_float2(a, b);
    }
#pragma unroll
    for (int p = 0; p < 4; p++) {
        int i = t + p * 256;
        int c = i >> 4;
        int k4 = (i & 15) * 4;
        float4 w4 = *(const float4*)&W2[c * EMB + k4];
        wsT[k4 + 0][c] = w4.x;
        wsT[k4 + 1][c] = w4.y;
        wsT[k4 + 2][c] = w4.z;
        wsT[k4 + 3][c] = w4.w;
    }
    __syncthreads();

    float o2A[RPT], o2B[RPT];
    float b2a = b2[ca], b2b = b2[cb];
#pragma unroll
    for (int j = 0; j < RPT; j++) { o2A[j] = b2a; o2B[j] = b2b; }

#pragma unroll
    for (int k2 = 0; k2 < 32; k2++) {
        int k = 2 * k2;
        float2 w0 = *(const float2*)&wsT[k][ca];
        float2 w1 = *(const float2*)&wsT[k + 1][ca];
#pragma unroll
        for (int j = 0; j < RPT; j++) {
            float2 x2 = *(const float2*)&xs[r0 + j][k];
            o2A[j] = fmaf(x2.x, w0.x, o2A[j]);
            o2A[j] = fmaf(x2.y, w1.x, o2A[j]);
            o2B[j] = fmaf(x2.x, w0.y, o2B[j]);
            o2B[j] = fmaf(x2.y, w1.y, o2B[j]);
        }
    }

#pragma unroll
    for (int j = 0; j < RPT; j++) {
        int gr = row0 + r0 + j;
        if (gr < nrows) {
            float a = fmaxf(o2A[j], 0.f);
            float b = fmaxf(o2B[j], 0.f);
            ((float2*)out)[gr * 32 + cg] = make_float2(a, b);
        }
    }
}

// ---------------- launch -----------------------------------------------------
extern "C" void kernel_launch(void* const* d_in, const int* in_sizes, int n_in,
                              void* d_out, int out_size)
{
    (void)n_in; (void)out_size;
    const float* left   = (const float*)d_in[0];
    const int*   ei     = (const int*)d_in[1];
    const float* ef     = (const float*)d_in[2];
    const float* right  = (const float*)d_in[3];
    const float* W_left  = (const float*)d_in[5];
    const float* b_left  = (const float*)d_in[6];
    const float* W_edge  = (const float*)d_in[7];
    const float* W_right = (const float*)d_in[8];
    const float* g1      = (const float*)d_in[9];
    const float* bt1     = (const float*)d_in[10];
    const float* W_final = (const float*)d_in[11];
    const float* b_final = (const float*)d_in[12];
    const float* g2      = (const float*)d_in[13];
    const float* bt2     = (const float*)d_in[14];
    const float* W1      = (const float*)d_in[15];
    const float* b1      = (const float*)d_in[16];
    const float* W2      = (const float*)d_in[17];
    const float* b2      = (const float*)d_in[18];
    float* out = (float*)d_out;

    int NL = in_sizes[0] / EMB;
    int NE = in_sizes[2];
    int NR = in_sizes[3] / EMB;

    float *pLP, *pRP, *pS, *pConv, *pDeg;
    cudaGetSymbolAddress((void**)&pLP, d_LP);
    cudaGetSymbolAddress((void**)&pRP, d_RP);
    cudaGetSymbolAddress((void**)&pS, d_S);
    cudaGetSymbolAddress((void**)&pConv, d_conv);
    cudaGetSymbolAddress((void**)&pDeg, d_deg);

    int nS4 = NR * EMB / 4;
    zero_kernel<<<(nS4 + 255) / 256, 256>>>(nS4, NR);
    gemm64_kernel<1><<<(NL + TROWS - 1) / TROWS, 256>>>(left, W_left, b_left, nullptr, pLP, NL);
    gemm64_kernel<0><<<(NR + TROWS - 1) / TROWS, 256>>>(right, W_right, nullptr, nullptr, pRP, NR);
    edge_stats_kernel<<<1184, 256>>>(ei, ef, W_edge, NE);
    bn_finalize_kernel<<<1, 64>>>(g1, bt1, (float)NE, 0, 0);
    {
        int npairs = (NE + 1) / 2;
        int nthr = npairs * 16;
        edge_scatter_kernel<<<(nthr + 255) / 256, 256>>>(ei, ef, W_edge, NE);
    }
    gemm64_kernel<2><<<(NR + TROWS - 1) / TROWS, 256>>>(pS, W_final, b_final, pDeg, pConv, NR);
    bn_finalize_kernel<<<1, 64>>>(g2, bt2, (float)NR, 128, 128);
    out_fused_kernel<<<(NR + TROWS - 1) / TROWS, 256>>>(pConv, right, W1, b1, W2, b2, out, NR);
}

// round 6
// speedup vs baseline: 8.7932x; 1.1094x over previous
#include <cuda_runtime.h>

#define EMB 64
#define NL_MAX 50000
#define NR_MAX 100000
#define NE_MAX 1000000
#define BN_EPS 1e-5f

#define WPAD 66         // wsT row pad: conflict-free float2 reads
#define TROWS 96        // rows per block tile
#define RPT 12          // rows per thread (TROWS / 8 warps)

// ---------------- scratch (static device globals) ----------------------------
__device__ float d_LP[NL_MAX * EMB];
__device__ float d_RP[NR_MAX * EMB];
__device__ float d_S[NR_MAX * EMB];
__device__ float d_conv[NR_MAX * EMB];
__device__ float d_deg[NR_MAX];
__device__ float d_stats[256];   // [0:64) sum1, [64:128) sq1, [128:192) sum2, [192:256) sq2
__device__ float d_sc[256];      // [0:64) scale1, [64:128) shift1, [128:192) scale2, [192:256) shift2

// ---------------- zero scratch (vectorized) ----------------------------------
__global__ void zero_kernel(int nS4, int nR) {
    int i = blockIdx.x * blockDim.x + threadIdx.x;
    if (i < nS4) ((float4*)d_S)[i] = make_float4(0.f, 0.f, 0.f, 0.f);
    if (i < nR) d_deg[i] = 0.f;
    if (i < 256) d_stats[i] = 0.f;
}

// ---------------- generic 64-wide GEMM --------------------------------------
// MODE 0: out = X@W.T ; 1: +bias ; 2: +deg*bias & bn2 stats ; 3: relu(+bias)
template <int MODE>
__global__ __launch_bounds__(256) void gemm64_kernel(
    const float* __restrict__ X, const float* __restrict__ W,
    const float* __restrict__ bias, const float* __restrict__ deg,
    float* __restrict__ out, int nrows)
{
    __shared__ float xs[TROWS][EMB];
    __shared__ float wsT[EMB][WPAD];
    __shared__ float red[128];

    int t = threadIdx.x;
    int cg = t & 31;
    int rg = t >> 5;
    int row0 = blockIdx.x * TROWS;
    int ca = 2 * cg, cb = 2 * cg + 1;
    int r0 = rg * RPT;

#pragma unroll
    for (int p = 0; p < 4; p++) {
        int i = t + p * 256;
        int c = i >> 4;
        int k4 = (i & 15) * 4;
        float4 w4 = *(const float4*)&W[c * EMB + k4];
        wsT[k4 + 0][c] = w4.x;
        wsT[k4 + 1][c] = w4.y;
        wsT[k4 + 2][c] = w4.z;
        wsT[k4 + 3][c] = w4.w;
    }
#pragma unroll
    for (int p = 0; p < TROWS / 16; p++) {
        int i = t + p * 256;
        int r = i >> 4;
        int c4 = (i & 15) * 4;
        int gr = row0 + r;
        float4 v = (gr < nrows) ? *(const float4*)&X[gr * EMB + c4]
                                : make_float4(0.f, 0.f, 0.f, 0.f);
        *(float4*)&xs[r][c4] = v;
    }
    __syncthreads();

    float accA[RPT], accB[RPT];
    float bca = 0.f, bcb = 0.f;
    if (MODE != 0) { bca = bias[ca]; bcb = bias[cb]; }
#pragma unroll
    for (int j = 0; j < RPT; j++) {
        if (MODE == 1 || MODE == 3) {
            accA[j] = bca; accB[j] = bcb;
        } else if (MODE == 2) {
            int gr = row0 + r0 + j;
            float dv = (gr < nrows) ? deg[gr] : 0.f;
            accA[j] = dv * bca; accB[j] = dv * bcb;
        } else {
            accA[j] = 0.f; accB[j] = 0.f;
        }
    }

    // k-step 4: x via broadcast LDS.128, w via 4 conflict-free LDS.64
#pragma unroll
    for (int kq = 0; kq < 16; kq++) {
        int k = 4 * kq;
        float2 w0 = *(const float2*)&wsT[k + 0][ca];
        float2 w1 = *(const float2*)&wsT[k + 1][ca];
        float2 w2 = *(const float2*)&wsT[k + 2][ca];
        float2 w3 = *(const float2*)&wsT[k + 3][ca];
#pragma unroll
        for (int j = 0; j < RPT; j++) {
            float4 x4 = *(const float4*)&xs[r0 + j][k];
            accA[j] = fmaf(x4.x, w0.x, accA[j]);
            accA[j] = fmaf(x4.y, w1.x, accA[j]);
            accA[j] = fmaf(x4.z, w2.x, accA[j]);
            accA[j] = fmaf(x4.w, w3.x, accA[j]);
            accB[j] = fmaf(x4.x, w0.y, accB[j]);
            accB[j] = fmaf(x4.y, w1.y, accB[j]);
            accB[j] = fmaf(x4.z, w2.y, accB[j]);
            accB[j] = fmaf(x4.w, w3.y, accB[j]);
        }
    }

    float sA = 0.f, qA = 0.f, sB = 0.f, qB = 0.f;
#pragma unroll
    for (int j = 0; j < RPT; j++) {
        int gr = row0 + r0 + j;
        if (gr < nrows) {
            float a = accA[j], b = accB[j];
            if (MODE == 3) { a = fmaxf(a, 0.f); b = fmaxf(b, 0.f); }
            ((float2*)out)[gr * 32 + cg] = make_float2(a, b);
            if (MODE == 2) { sA += a; qA += a * a; sB += b; qB += b * b; }
        }
    }

    if (MODE == 2) {
        if (t < 128) red[t] = 0.f;
        __syncthreads();
        atomicAdd(&red[ca], sA);
        atomicAdd(&red[64 + ca], qA);
        atomicAdd(&red[cb], sB);
        atomicAdd(&red[64 + cb], qB);
        __syncthreads();
        if (t < 128) atomicAdd(&d_stats[128 + t], red[t]);
    }
}

// ---------------- edge pass 1: bn1 stats + degree (ILP x2, 192-thr blocks) --
__global__ __launch_bounds__(192) void edge_stats_kernel(
    const int* __restrict__ ei, const float* __restrict__ ef,
    const float* __restrict__ Wedge, int NE)
{
    int t = threadIdx.x;
    int g = t & 15;
    int slot = blockIdx.x * 12 + (t >> 4);
    int step = gridDim.x * 12;
    float4 we = ((const float4*)Wedge)[g];
    float4 sum = make_float4(0.f, 0.f, 0.f, 0.f);
    float4 sq = make_float4(0.f, 0.f, 0.f, 0.f);

    for (int e = slot; e < NE; e += 2 * step) {
        int eB = e + step;
        bool hasB = eB < NE;
        int eBc = hasB ? eB : e;
        int i0a = ei[e];
        int i1a = ei[NE + e];
        float fa = ef[e];
        int i0b = ei[eBc];
        int i1b = ei[NE + eBc];
        float fb = ef[eBc];
        float4 lpA = ((const float4*)d_LP)[i0a * 16 + g];
        float4 rpA = ((const float4*)d_RP)[i1a * 16 + g];
        float4 lpB = ((const float4*)d_LP)[i0b * 16 + g];
        float4 rpB = ((const float4*)d_RP)[i1b * 16 + g];

        float4 jA;
        jA.x = fmaf(fa, we.x, lpA.x + rpA.x);
        jA.y = fmaf(fa, we.y, lpA.y + rpA.y);
        jA.z = fmaf(fa, we.z, lpA.z + rpA.z);
        jA.w = fmaf(fa, we.w, lpA.w + rpA.w);
        sum.x += jA.x; sum.y += jA.y; sum.z += jA.z; sum.w += jA.w;
        sq.x += jA.x * jA.x; sq.y += jA.y * jA.y;
        sq.z += jA.z * jA.z; sq.w += jA.w * jA.w;

        float m = hasB ? 1.f : 0.f;
        float4 jB;
        jB.x = fmaf(fb, we.x, lpB.x + rpB.x);
        jB.y = fmaf(fb, we.y, lpB.y + rpB.y);
        jB.z = fmaf(fb, we.z, lpB.z + rpB.z);
        jB.w = fmaf(fb, we.w, lpB.w + rpB.w);
        sum.x += m * jB.x; sum.y += m * jB.y;
        sum.z += m * jB.z; sum.w += m * jB.w;
        sq.x += m * jB.x * jB.x; sq.y += m * jB.y * jB.y;
        sq.z += m * jB.z * jB.z; sq.w += m * jB.w * jB.w;

        if (g == 0) {
            atomicAdd(&d_deg[i1a], 1.f);
            if (hasB) atomicAdd(&d_deg[i1b], 1.f);
        }
    }

    __shared__ float red[128];
    if (t < 128) red[t] = 0.f;
    __syncthreads();
    atomicAdd(&red[4 * g + 0], sum.x);
    atomicAdd(&red[4 * g + 1], sum.y);
    atomicAdd(&red[4 * g + 2], sum.z);
    atomicAdd(&red[4 * g + 3], sum.w);
    atomicAdd(&red[64 + 4 * g + 0], sq.x);
    atomicAdd(&red[64 + 4 * g + 1], sq.y);
    atomicAdd(&red[64 + 4 * g + 2], sq.z);
    atomicAdd(&red[64 + 4 * g + 3], sq.w);
    __syncthreads();
    if (t < 128) atomicAdd(&d_stats[t], red[t]);
}

// ---------------- batchnorm finalize ----------------------------------------
__global__ void bn_finalize_kernel(const float* __restrict__ gamma,
                                   const float* __restrict__ beta,
                                   float cnt, int soff, int ooff)
{
    int c = threadIdx.x;
    if (c < 64) {
        float mean = d_stats[soff + c] / cnt;
        float var = d_stats[soff + 64 + c] / cnt - mean * mean;
        float sc = gamma[c] * rsqrtf(var + BN_EPS);
        d_sc[ooff + c] = sc;
        d_sc[ooff + 64 + c] = beta[c] - mean * sc;
    }
}

// ---------------- edge pass 2: bn1+relu joint, scatter into S (ILP x2) ------
__global__ __launch_bounds__(192) void edge_scatter_kernel(
    const int* __restrict__ ei, const float* __restrict__ ef,
    const float* __restrict__ Wedge, int NE)
{
    int tid = blockIdx.x * 192 + threadIdx.x;
    int p = tid >> 4;
    int g = tid & 15;
    int eA = 2 * p;
    if (eA >= NE) return;
    int eB = eA + 1;
    bool hasB = eB < NE;
    int eBc = hasB ? eB : eA;

    float4 we = ((const float4*)Wedge)[g];
    float4 s = ((const float4*)d_sc)[g];
    float4 sh = ((const float4*)d_sc)[16 + g];

    int i0a = ei[eA];
    int i1a = ei[NE + eA];
    float fa = ef[eA];
    int i0b = ei[eBc];
    int i1b = ei[NE + eBc];
    float fb = ef[eBc];
    float4 lpA = ((const float4*)d_LP)[i0a * 16 + g];
    float4 rpA = ((const float4*)d_RP)[i1a * 16 + g];
    float4 lpB = ((const float4*)d_LP)[i0b * 16 + g];
    float4 rpB = ((const float4*)d_RP)[i1b * 16 + g];

    float4 vA;
    vA.x = fmaxf(fmaf(fmaf(fa, we.x, lpA.x + rpA.x), s.x, sh.x), 0.f);
    vA.y = fmaxf(fmaf(fmaf(fa, we.y, lpA.y + rpA.y), s.y, sh.y), 0.f);
    vA.z = fmaxf(fmaf(fmaf(fa, we.z, lpA.z + rpA.z), s.z, sh.z), 0.f);
    vA.w = fmaxf(fmaf(fmaf(fa, we.w, lpA.w + rpA.w), s.w, sh.w), 0.f);
    float* pa = &d_S[i1a * EMB + 4 * g];
    asm volatile("red.global.add.v4.f32 [%0], {%1,%2,%3,%4};"
                 :: "l"(pa), "f"(vA.x), "f"(vA.y), "f"(vA.z), "f"(vA.w) : "memory");

    if (hasB) {
        float4 vB;
        vB.x = fmaxf(fmaf(fmaf(fb, we.x, lpB.x + rpB.x), s.x, sh.x), 0.f);
        vB.y = fmaxf(fmaf(fmaf(fb, we.y, lpB.y + rpB.y), s.y, sh.y), 0.f);
        vB.z = fmaxf(fmaf(fmaf(fb, we.z, lpB.z + rpB.z), s.z, sh.z), 0.f);
        vB.w = fmaxf(fmaf(fmaf(fb, we.w, lpB.w + rpB.w), s.w, sh.w), 0.f);
        float* pb = &d_S[i1b * EMB + 4 * g];
        asm volatile("red.global.add.v4.f32 [%0], {%1,%2,%3,%4};"
                     :: "l"(pb), "f"(vB.x), "f"(vB.y), "f"(vB.z), "f"(vB.w) : "memory");
    }
}

// ---------------- fused output layers ----------------------------------------
__global__ __launch_bounds__(256) void out_fused_kernel(
    const float* __restrict__ conv, const float* __restrict__ right,
    const float* __restrict__ W1, const float* __restrict__ b1,
    const float* __restrict__ W2, const float* __restrict__ b2,
    float* __restrict__ out, int nrows)
{
    __shared__ float xs[TROWS][EMB];
    __shared__ float wsT[EMB][WPAD];

    int t = threadIdx.x;
    int cg = t & 31;
    int rg = t >> 5;
    int row0 = blockIdx.x * TROWS;
    int ca = 2 * cg, cb = 2 * cg + 1;
    int r0 = rg * RPT;

    float accA[RPT], accB[RPT];
    float bca = b1[ca], bcb = b1[cb];
#pragma unroll
    for (int j = 0; j < RPT; j++) { accA[j] = bca; accB[j] = bcb; }

#pragma unroll
    for (int phase = 0; phase < 2; phase++) {
        int koff = phase * 64;
#pragma unroll
        for (int p = 0; p < 4; p++) {
            int i = t + p * 256;
            int c = i >> 4;
            int k4 = (i & 15) * 4;
            float4 w4 = *(const float4*)&W1[c * 128 + koff + k4];
            wsT[k4 + 0][c] = w4.x;
            wsT[k4 + 1][c] = w4.y;
            wsT[k4 + 2][c] = w4.z;
            wsT[k4 + 3][c] = w4.w;
        }
#pragma unroll
        for (int p = 0; p < TROWS / 16; p++) {
            int i = t + p * 256;
            int r = i >> 4;
            int c4 = (i & 15) * 4;
            int gr = row0 + r;
            float4 v;
            if (gr < nrows) {
                if (phase == 0) {
                    v = *(const float4*)&conv[gr * EMB + c4];
                    v.x = v.x * d_sc[128 + c4 + 0] + d_sc[192 + c4 + 0];
                    v.y = v.y * d_sc[128 + c4 + 1] + d_sc[192 + c4 + 1];
                    v.z = v.z * d_sc[128 + c4 + 2] + d_sc[192 + c4 + 2];
                    v.w = v.w * d_sc[128 + c4 + 3] + d_sc[192 + c4 + 3];
                } else {
                    v = *(const float4*)&right[gr * EMB + c4];
                }
            } else {
                v = make_float4(0.f, 0.f, 0.f, 0.f);
            }
            *(float4*)&xs[r][c4] = v;
        }
        __syncthreads();

#pragma unroll
        for (int kq = 0; kq < 16; kq++) {
            int k = 4 * kq;
            float2 w0 = *(const float2*)&wsT[k + 0][ca];
            float2 w1 = *(const float2*)&wsT[k + 1][ca];
            float2 w2 = *(const float2*)&wsT[k + 2][ca];
            float2 w3 = *(const float2*)&wsT[k + 3][ca];
#pragma unroll
            for (int j = 0; j < RPT; j++) {
                float4 x4 = *(const float4*)&xs[r0 + j][k];
                accA[j] = fmaf(x4.x, w0.x, accA[j]);
                accA[j] = fmaf(x4.y, w1.x, accA[j]);
                accA[j] = fmaf(x4.z, w2.x, accA[j]);
                accA[j] = fmaf(x4.w, w3.x, accA[j]);
                accB[j] = fmaf(x4.x, w0.y, accB[j]);
                accB[j] = fmaf(x4.y, w1.y, accB[j]);
                accB[j] = fmaf(x4.z, w2.y, accB[j]);
                accB[j] = fmaf(x4.w, w3.y, accB[j]);
            }
        }
        __syncthreads();
    }

    // h -> shared (relu); stage W2; second GEMM in-block
#pragma unroll
    for (int j = 0; j < RPT; j++) {
        float a = fmaxf(accA[j], 0.f);
        float b = fmaxf(accB[j], 0.f);
        *(float2*)&xs[r0 + j][ca] = make_float2(a, b);
    }
#pragma unroll
    for (int p = 0; p < 4; p++) {
        int i = t + p * 256;
        int c = i >> 4;
        int k4 = (i & 15) * 4;
        float4 w4 = *(const float4*)&W2[c * EMB + k4];
        wsT[k4 + 0][c] = w4.x;
        wsT[k4 + 1][c] = w4.y;
        wsT[k4 + 2][c] = w4.z;
        wsT[k4 + 3][c] = w4.w;
    }
    __syncthreads();

    float o2A[RPT], o2B[RPT];
    float b2a = b2[ca], b2b = b2[cb];
#pragma unroll
    for (int j = 0; j < RPT; j++) { o2A[j] = b2a; o2B[j] = b2b; }

#pragma unroll
    for (int kq = 0; kq < 16; kq++) {
        int k = 4 * kq;
        float2 w0 = *(const float2*)&wsT[k + 0][ca];
        float2 w1 = *(const float2*)&wsT[k + 1][ca];
        float2 w2 = *(const float2*)&wsT[k + 2][ca];
        float2 w3 = *(const float2*)&wsT[k + 3][ca];
#pragma unroll
        for (int j = 0; j < RPT; j++) {
            float4 x4 = *(const float4*)&xs[r0 + j][k];
            o2A[j] = fmaf(x4.x, w0.x, o2A[j]);
            o2A[j] = fmaf(x4.y, w1.x, o2A[j]);
            o2A[j] = fmaf(x4.z, w2.x, o2A[j]);
            o2A[j] = fmaf(x4.w, w3.x, o2A[j]);
            o2B[j] = fmaf(x4.x, w0.y, o2B[j]);
            o2B[j] = fmaf(x4.y, w1.y, o2B[j]);
            o2B[j] = fmaf(x4.z, w2.y, o2B[j]);
            o2B[j] = fmaf(x4.w, w3.y, o2B[j]);
        }
    }

#pragma unroll
    for (int j = 0; j < RPT; j++) {
        int gr = row0 + r0 + j;
        if (gr < nrows) {
            float a = fmaxf(o2A[j], 0.f);
            float b = fmaxf(o2B[j], 0.f);
            ((float2*)out)[gr * 32 + cg] = make_float2(a, b);
        }
    }
}

// ---------------- launch -----------------------------------------------------
extern "C" void kernel_launch(void* const* d_in, const int* in_sizes, int n_in,
                              void* d_out, int out_size)
{
    (void)n_in; (void)out_size;
    const float* left   = (const float*)d_in[0];
    const int*   ei     = (const int*)d_in[1];
    const float* ef     = (const float*)d_in[2];
    const float* right  = (const float*)d_in[3];
    const float* W_left  = (const float*)d_in[5];
    const float* b_left  = (const float*)d_in[6];
    const float* W_edge  = (const float*)d_in[7];
    const float* W_right = (const float*)d_in[8];
    const float* g1      = (const float*)d_in[9];
    const float* bt1     = (const float*)d_in[10];
    const float* W_final = (const float*)d_in[11];
    const float* b_final = (const float*)d_in[12];
    const float* g2      = (const float*)d_in[13];
    const float* bt2     = (const float*)d_in[14];
    const float* W1      = (const float*)d_in[15];
    const float* b1      = (const float*)d_in[16];
    const float* W2      = (const float*)d_in[17];
    const float* b2      = (const float*)d_in[18];
    float* out = (float*)d_out;

    int NL = in_sizes[0] / EMB;
    int NE = in_sizes[2];
    int NR = in_sizes[3] / EMB;

    float *pLP, *pRP, *pS, *pConv, *pDeg;
    cudaGetSymbolAddress((void**)&pLP, d_LP);
    cudaGetSymbolAddress((void**)&pRP, d_RP);
    cudaGetSymbolAddress((void**)&pS, d_S);
    cudaGetSymbolAddress((void**)&pConv, d_conv);
    cudaGetSymbolAddress((void**)&pDeg, d_deg);

    int nS4 = NR * EMB / 4;
    zero_kernel<<<(nS4 + 255) / 256, 256>>>(nS4, NR);
    gemm64_kernel<1><<<(NL + TROWS - 1) / TROWS, 256>>>(left, W_left, b_left, nullptr, pLP, NL);
    gemm64_kernel<0><<<(NR + TROWS - 1) / TROWS, 256>>>(right, W_right, nullptr, nullptr, pRP, NR);
    edge_stats_kernel<<<1184, 192>>>(ei, ef, W_edge, NE);
    bn_finalize_kernel<<<1, 64>>>(g1, bt1, (float)NE, 0, 0);
    {
        int npairs = (NE + 1) / 2;
        int nthr = npairs * 16;
        edge_scatter_kernel<<<(nthr + 191) / 192, 192>>>(ei, ef, W_edge, NE);
    }
    gemm64_kernel<2><<<(NR + TROWS - 1) / TROWS, 256>>>(pS, W_final, b_final, pDeg, pConv, NR);
    bn_finalize_kernel<<<1, 64>>>(g2, bt2, (float)NR, 128, 128);
    out_fused_kernel<<<(NR + TROWS - 1) / TROWS, 256>>>(pConv, right, W1, b1, W2, b2, out, NR);
}